// round 1
// baseline (speedup 1.0000x reference)
#include <cuda_runtime.h>

// Problem constants (fixed by the reference)
#define SEQ_LEN   512
#define EMB       768
#define NLAB      9
#define FEAT      2354            // 3*768 + 50
#define WDIM      50
#define MAXW      16
#define NSPANS    32768

// Scratch tables (allocation-free rule: __device__ globals)
__device__ float g_Ps[SEQ_LEN * NLAB];          // start-token projection
__device__ float g_Pe[SEQ_LEN * NLAB];          // end-token projection
__device__ float g_Pa[SEQ_LEN * NLAB];          // avg-slice per-token projection
__device__ float g_Pc[(SEQ_LEN + 1) * NLAB];    // exclusive prefix sums of g_Pa
__device__ float g_Pwb[(MAXW + 1) * NLAB];      // width_table @ Ww^T + b

// ---------------------------------------------------------------------------
// Kernel 1: per-token projections against the 3 contiguous 768-wide W slices.
// One block per token. Seq row staged in smem; each warp owns a subset of the
// 27 (slice,label) dot products, lanes stride the 768 dim, warp-reduce.
// ---------------------------------------------------------------------------
__global__ void token_proj_kernel(const float* __restrict__ seq,
                                  const float* __restrict__ W) {
    __shared__ float srow[EMB];
    const int s = blockIdx.x;
    const float4* row4 = reinterpret_cast<const float4*>(seq + (size_t)s * EMB);
    for (int k = threadIdx.x; k < EMB / 4; k += blockDim.x) {
        float4 v = row4[k];
        srow[4 * k + 0] = v.x; srow[4 * k + 1] = v.y;
        srow[4 * k + 2] = v.z; srow[4 * k + 3] = v.w;
    }
    __syncthreads();

    const int warp = threadIdx.x >> 5;
    const int lane = threadIdx.x & 31;
    const int nwarps = blockDim.x >> 5;

    for (int j = warp; j < 3 * NLAB; j += nwarps) {
        const int slice = j / NLAB;        // 0=start, 1=end, 2=avg
        const int l     = j % NLAB;
        const float* wrow = W + (size_t)l * FEAT + slice * EMB;
        float acc = 0.f;
        #pragma unroll
        for (int k = lane; k < EMB; k += 32)
            acc += srow[k] * __ldg(wrow + k);
        #pragma unroll
        for (int o = 16; o > 0; o >>= 1)
            acc += __shfl_down_sync(0xffffffffu, acc, o);
        if (lane == 0) {
            float* dst = (slice == 0) ? g_Ps : (slice == 1) ? g_Pe : g_Pa;
            dst[s * NLAB + l] = acc;
        }
    }
}

// ---------------------------------------------------------------------------
// Kernel 2: (a) width projection + bias -> g_Pwb  (17*9 tiny dots of 50)
//           (b) per-label exclusive prefix sum of g_Pa -> g_Pc, fp64 carry
//               (warp-segmented scan: 16 chunks of 32, log-depth inside chunk)
// Single block, 320 threads (warps 0..8 scan labels 0..8).
// ---------------------------------------------------------------------------
__global__ void scan_width_kernel(const float* __restrict__ wt,
                                  const float* __restrict__ W,
                                  const float* __restrict__ b) {
    const int tid = threadIdx.x;

    // (a) width/bias table
    if (tid < (MAXW + 1) * NLAB) {
        const int w = tid / NLAB;
        const int l = tid % NLAB;
        const float* wrow = W + (size_t)l * FEAT + 3 * EMB;
        float acc = __ldg(b + l);
        #pragma unroll
        for (int k = 0; k < WDIM; k++)
            acc += __ldg(wt + w * WDIM + k) * __ldg(wrow + k);
        g_Pwb[tid] = acc;
    }

    // (b) scans
    const int warp = tid >> 5;
    const int lane = tid & 31;
    if (warp < NLAB) {
        const int l = warp;
        if (lane == 0) g_Pc[l] = 0.f;   // Pc[0] = 0
        double carry = 0.0;
        #pragma unroll
        for (int c = 0; c < SEQ_LEN / 32; c++) {
            const int i = c * 32 + lane;
            double x = (double)g_Pa[i * NLAB + l];
            #pragma unroll
            for (int o = 1; o < 32; o <<= 1) {
                double y = __shfl_up_sync(0xffffffffu, x, o);
                if (lane >= o) x += y;
            }
            const double v = carry + x;       // inclusive prefix through token i
            g_Pc[(i + 1) * NLAB + l] = (float)v;
            carry = __shfl_sync(0xffffffffu, v, 31);
        }
    }
}

// ---------------------------------------------------------------------------
// Kernel 3: assemble logits. One thread per output element (span*9 + label).
// Writes fully coalesced; index loads broadcast (9 threads share a span);
// table lookups hit L1 (~56 KB of tables).
// ---------------------------------------------------------------------------
__global__ void assemble_kernel(const int* __restrict__ st,
                                const int* __restrict__ en,
                                const int* __restrict__ wd,
                                float* __restrict__ out) {
    const int tid = blockIdx.x * blockDim.x + threadIdx.x;
    if (tid >= NSPANS * NLAB) return;
    const int span = tid / NLAB;
    const int l    = tid - span * NLAB;
    const int s = __ldg(st + span);
    const int e = __ldg(en + span);
    const int w = __ldg(wd + span);
    const float avg = (g_Pc[e * NLAB + l] - g_Pc[s * NLAB + l]) / (float)w;
    out[tid] = g_Ps[s * NLAB + l] + g_Pe[e * NLAB + l] + avg + g_Pwb[w * NLAB + l];
}

// ---------------------------------------------------------------------------
extern "C" void kernel_launch(void* const* d_in, const int* in_sizes, int n_in,
                              void* d_out, int out_size) {
    const float* seq = (const float*)d_in[0];   // [1,512,768]
    const int*   st  = (const int*)  d_in[1];   // [32768]
    const int*   en  = (const int*)  d_in[2];   // [32768]
    const int*   wd  = (const int*)  d_in[3];   // [32768]
    const float* wt  = (const float*)d_in[4];   // [17,50]
    const float* W   = (const float*)d_in[5];   // [9,2354]
    const float* b   = (const float*)d_in[6];   // [9]
    float* out = (float*)d_out;                 // [32768,9]

    token_proj_kernel<<<SEQ_LEN, 256>>>(seq, W);
    scan_width_kernel<<<1, 320>>>(wt, W, b);
    const int total = NSPANS * NLAB;
    assemble_kernel<<<(total + 255) / 256, 256>>>(st, en, wd, out);
}

// round 2
// speedup vs baseline: 1.2326x; 1.2326x over previous
#include <cuda_runtime.h>

// Problem constants (fixed by the reference)
#define SEQ_LEN   512
#define EMB       768
#define NLAB      9
#define FEAT      2354            // 3*768 + 50
#define WDIM      50
#define MAXW      16
#define NSPANS    32768

// Scratch tables (allocation-free rule: __device__ globals)
__device__ float g_Ps[SEQ_LEN * NLAB];          // start-token projection
__device__ float g_Pe[SEQ_LEN * NLAB];          // end-token projection
__device__ float g_Pa[SEQ_LEN * NLAB];          // avg-slice per-token projection
__device__ float g_Pc[(SEQ_LEN + 1) * NLAB];    // inclusive-prefix table (Pc[0]=0)
__device__ float g_Pwb[(MAXW + 1) * NLAB];      // width_table @ Ww^T + b

// ---------------------------------------------------------------------------
// Kernel 1: warp-per-token. The warp loads the token's 768-float row once
// (float4 per lane, 6 chunks) and FMAs it against all 27 W rows
// (float2 loads: FEAT=2354 is ==2 mod 4, so odd-label rows are only
// 8-byte aligned). 27 independent accumulator chains + ~55 loads in flight
// per iteration -> high ILP/MLP per warp. 512 blocks x 32 threads.
// ---------------------------------------------------------------------------
__global__ void __launch_bounds__(32)
token_proj_kernel(const float* __restrict__ seq, const float* __restrict__ W) {
    const int s    = blockIdx.x;
    const int lane = threadIdx.x;
    const float* row = seq + (size_t)s * EMB;

    float acc[27];
    #pragma unroll
    for (int j = 0; j < 27; j++) acc[j] = 0.f;

    #pragma unroll
    for (int c = 0; c < 6; c++) {
        const int k = c * 128 + lane * 4;                 // 4 floats per lane
        const float4 sv = *reinterpret_cast<const float4*>(row + k);
        #pragma unroll
        for (int j = 0; j < 27; j++) {
            const int off = (j % 9) * FEAT + (j / 9) * EMB;   // compile-time
            const float2 w0 = __ldg(reinterpret_cast<const float2*>(W + off + k));
            const float2 w1 = __ldg(reinterpret_cast<const float2*>(W + off + k + 2));
            acc[j] += sv.x * w0.x + sv.y * w0.y + sv.z * w1.x + sv.w * w1.y;
        }
    }

    #pragma unroll
    for (int j = 0; j < 27; j++) {
        float v = acc[j];
        #pragma unroll
        for (int o = 16; o > 0; o >>= 1)
            v += __shfl_down_sync(0xffffffffu, v, o);
        if (lane == 0) {
            const int slice = j / 9, l = j % 9;
            float* dst = (slice == 0) ? g_Ps : (slice == 1) ? g_Pe : g_Pa;
            dst[s * NLAB + l] = v;
        }
    }
}

// ---------------------------------------------------------------------------
// Kernel 2: one block, 512 threads (thread = token).
//  (a) width projection + bias -> g_Pwb (17*9 tiny dots of 50), tid<153
//  (b) 9 parallel block-wide inclusive scans over 512 tokens:
//      warp-scan (fp32, 5 levels) -> 9-thread serial combine of the 16
//      warp totals -> add exclusive carry. All parallel, no fp64.
// ---------------------------------------------------------------------------
__global__ void __launch_bounds__(512)
scan_width_kernel(const float* __restrict__ wt,
                  const float* __restrict__ W,
                  const float* __restrict__ b) {
    __shared__ float tot[16][NLAB];     // per-warp inclusive totals
    __shared__ float carry[16][NLAB];   // exclusive inter-warp carries

    const int tid  = threadIdx.x;
    const int lane = tid & 31;
    const int warp = tid >> 5;

    // (a) width/bias table
    if (tid < (MAXW + 1) * NLAB) {
        const int w = tid / NLAB;
        const int l = tid % NLAB;
        const float* wrow = W + (size_t)l * FEAT + 3 * EMB;
        float acc = __ldg(b + l);
        #pragma unroll
        for (int k = 0; k < WDIM; k++)
            acc += __ldg(wt + w * WDIM + k) * __ldg(wrow + k);
        g_Pwb[tid] = acc;
    }

    // (b) load this token's 9 projections
    float a[NLAB];
    #pragma unroll
    for (int l = 0; l < NLAB; l++) a[l] = g_Pa[tid * NLAB + l];

    // 9 independent warp inclusive scans (token dim = lanes)
    #pragma unroll
    for (int l = 0; l < NLAB; l++) {
        float x = a[l];
        #pragma unroll
        for (int o = 1; o < 32; o <<= 1) {
            const float y = __shfl_up_sync(0xffffffffu, x, o);
            if (lane >= o) x += y;
        }
        a[l] = x;
    }
    if (lane == 31) {
        #pragma unroll
        for (int l = 0; l < NLAB; l++) tot[warp][l] = a[l];
    }
    __syncthreads();

    // serial combine of 16 warp totals, one thread per label
    if (tid < NLAB) {
        float r = 0.f;
        #pragma unroll
        for (int w = 0; w < 16; w++) { carry[w][tid] = r; r += tot[w][tid]; }
        g_Pc[tid] = 0.f;                       // Pc[0] = 0
    }
    __syncthreads();

    #pragma unroll
    for (int l = 0; l < NLAB; l++)
        g_Pc[(tid + 1) * NLAB + l] = a[l] + carry[warp][l];
}

// ---------------------------------------------------------------------------
// Kernel 3: assemble logits. One thread per output element (span*9 + label).
// Coalesced stores; index loads broadcast within 9-thread groups; table
// lookups hit L1 (~56 KB of tables).
// ---------------------------------------------------------------------------
__global__ void __launch_bounds__(256)
assemble_kernel(const int* __restrict__ st,
                const int* __restrict__ en,
                const int* __restrict__ wd,
                float* __restrict__ out) {
    const int tid = blockIdx.x * blockDim.x + threadIdx.x;
    if (tid >= NSPANS * NLAB) return;
    const int span = tid / NLAB;
    const int l    = tid - span * NLAB;
    const int s = __ldg(st + span);
    const int e = __ldg(en + span);
    const int w = __ldg(wd + span);
    const float diff = g_Pc[e * NLAB + l] - g_Pc[s * NLAB + l];
    out[tid] = g_Ps[s * NLAB + l] + g_Pe[e * NLAB + l]
             + __fdividef(diff, (float)w) + g_Pwb[w * NLAB + l];
}

// ---------------------------------------------------------------------------
extern "C" void kernel_launch(void* const* d_in, const int* in_sizes, int n_in,
                              void* d_out, int out_size) {
    const float* seq = (const float*)d_in[0];   // [1,512,768]
    const int*   st  = (const int*)  d_in[1];   // [32768]
    const int*   en  = (const int*)  d_in[2];   // [32768]
    const int*   wd  = (const int*)  d_in[3];   // [32768]
    const float* wt  = (const float*)d_in[4];   // [17,50]
    const float* W   = (const float*)d_in[5];   // [9,2354]
    const float* b   = (const float*)d_in[6];   // [9]
    float* out = (float*)d_out;                 // [32768,9]

    token_proj_kernel<<<SEQ_LEN, 32>>>(seq, W);
    scan_width_kernel<<<1, 512>>>(wt, W, b);
    const int total = NSPANS * NLAB;
    assemble_kernel<<<(total + 255) / 256, 256>>>(st, en, wd, out);
}

// round 3
// speedup vs baseline: 1.2966x; 1.0520x over previous
#include <cuda_runtime.h>

// Problem constants (fixed by the reference)
#define SEQ_LEN   512
#define EMB       768
#define NLAB      9
#define FEAT      2354            // 3*768 + 50
#define WDIM      50
#define MAXW      16
#define NSPANS    32768
#define NCHUNK    6               // 768 / 128
#define CHUNK     128

// Scratch (allocation-free rule: __device__ globals)
__device__ float g_part[NCHUNK * SEQ_LEN * 27]; // split-K partial dots
__device__ float g_Ps[SEQ_LEN * NLAB];          // start-token projection
__device__ float g_Pe[SEQ_LEN * NLAB];          // end-token projection
__device__ float g_Pa[SEQ_LEN * NLAB];          // avg-slice per-token projection
__device__ float g_Pc[(SEQ_LEN + 1) * NLAB];    // prefix table (Pc[0]=0)
__device__ float g_Pwb[(MAXW + 1) * NLAB];      // width_table @ Ww^T + b

// ---------------------------------------------------------------------------
// Kernel 1: split-K token projection.
// grid = (64 token-groups, 6 k-chunks), block = 256 (8 warps = 8 tokens).
// Block stages its 27x128-float W chunk in smem once (8x reuse across the
// token-warps -> W L2 traffic 42MB -> 5.3MB). Each warp: one LDG.128 of its
// seq chunk, 27 conflict-free LDS.128 + FMA, 27 shfl reductions, partial out.
// ---------------------------------------------------------------------------
__global__ void __launch_bounds__(256)
token_proj_kernel(const float* __restrict__ seq, const float* __restrict__ W) {
    __shared__ __align__(16) float sw[27 * CHUNK];

    const int chunk = blockIdx.y;
    const int kbase = chunk * CHUNK;

    // Stage W chunk: 27 rows x 128 floats, float2 (rows only 8B-aligned).
    for (int i = threadIdx.x; i < 27 * (CHUNK / 2); i += 256) {
        const int j = i >> 6;                 // 0..26
        const int p = (i & 63) * 2;           // 0..126
        const int l = j % 9, sl = j / 9;
        const float2 v = __ldg(reinterpret_cast<const float2*>(
            W + (size_t)l * FEAT + sl * EMB + kbase + p));
        sw[j * CHUNK + p]     = v.x;
        sw[j * CHUNK + p + 1] = v.y;
    }
    __syncthreads();

    const int warp = threadIdx.x >> 5;
    const int lane = threadIdx.x & 31;
    const int tok  = blockIdx.x * 8 + warp;

    const float4 sv = *reinterpret_cast<const float4*>(
        seq + (size_t)tok * EMB + kbase + lane * 4);

    float acc[27];
    #pragma unroll
    for (int j = 0; j < 27; j++) {
        const float4 w = *reinterpret_cast<const float4*>(sw + j * CHUNK + lane * 4);
        acc[j] = sv.x * w.x + sv.y * w.y + sv.z * w.z + sv.w * w.w;
    }

    #pragma unroll
    for (int j = 0; j < 27; j++) {
        #pragma unroll
        for (int o = 16; o > 0; o >>= 1)
            acc[j] += __shfl_down_sync(0xffffffffu, acc[j], o);
    }

    if (lane == 0) {
        float* dst = g_part + ((size_t)chunk * SEQ_LEN + tok) * 27;
        #pragma unroll
        for (int j = 0; j < 27; j++) dst[j] = acc[j];
    }
}

// ---------------------------------------------------------------------------
// Kernel 1b: fold the 6 k-chunk partials -> final Ps/Pe/Pa. Coalesced.
// ---------------------------------------------------------------------------
__global__ void __launch_bounds__(256)
reduce_kernel() {
    const int i = blockIdx.x * blockDim.x + threadIdx.x;   // 0..13823
    if (i >= SEQ_LEN * 27) return;
    float s = 0.f;
    #pragma unroll
    for (int c = 0; c < NCHUNK; c++)
        s += g_part[c * SEQ_LEN * 27 + i];
    const int tok = i / 27;
    const int j   = i - tok * 27;
    const int l = j % 9, sl = j / 9;
    float* dst = (sl == 0) ? g_Ps : (sl == 1) ? g_Pe : g_Pa;
    dst[tok * NLAB + l] = s;
}

// ---------------------------------------------------------------------------
// Kernel 2: one block, 512 threads (thread = token).
//  (a) width projection + bias -> g_Pwb
//  (b) 9 parallel block-wide inclusive scans of g_Pa -> g_Pc
// ---------------------------------------------------------------------------
__global__ void __launch_bounds__(512)
scan_width_kernel(const float* __restrict__ wt,
                  const float* __restrict__ W,
                  const float* __restrict__ b) {
    __shared__ float tot[16][NLAB];
    __shared__ float carry[16][NLAB];

    const int tid  = threadIdx.x;
    const int lane = tid & 31;
    const int warp = tid >> 5;

    if (tid < (MAXW + 1) * NLAB) {
        const int w = tid / NLAB;
        const int l = tid % NLAB;
        const float* wrow = W + (size_t)l * FEAT + 3 * EMB;
        float acc = __ldg(b + l);
        #pragma unroll
        for (int k = 0; k < WDIM; k++)
            acc += __ldg(wt + w * WDIM + k) * __ldg(wrow + k);
        g_Pwb[tid] = acc;
    }

    float a[NLAB];
    #pragma unroll
    for (int l = 0; l < NLAB; l++) a[l] = g_Pa[tid * NLAB + l];

    #pragma unroll
    for (int l = 0; l < NLAB; l++) {
        float x = a[l];
        #pragma unroll
        for (int o = 1; o < 32; o <<= 1) {
            const float y = __shfl_up_sync(0xffffffffu, x, o);
            if (lane >= o) x += y;
        }
        a[l] = x;
    }
    if (lane == 31) {
        #pragma unroll
        for (int l = 0; l < NLAB; l++) tot[warp][l] = a[l];
    }
    __syncthreads();

    if (tid < NLAB) {
        float r = 0.f;
        #pragma unroll
        for (int w = 0; w < 16; w++) { carry[w][tid] = r; r += tot[w][tid]; }
        g_Pc[tid] = 0.f;
    }
    __syncthreads();

    #pragma unroll
    for (int l = 0; l < NLAB; l++)
        g_Pc[(tid + 1) * NLAB + l] = a[l] + carry[warp][l];
}

// ---------------------------------------------------------------------------
// Kernel 3: assemble logits. Thread = output element. Coalesced stores,
// broadcast index loads, L1-resident table lookups.
// ---------------------------------------------------------------------------
__global__ void __launch_bounds__(256)
assemble_kernel(const int* __restrict__ st,
                const int* __restrict__ en,
                const int* __restrict__ wd,
                float* __restrict__ out) {
    const int tid = blockIdx.x * blockDim.x + threadIdx.x;
    if (tid >= NSPANS * NLAB) return;
    const int span = tid / NLAB;
    const int l    = tid - span * NLAB;
    const int s = __ldg(st + span);
    const int e = __ldg(en + span);
    const int w = __ldg(wd + span);
    const float diff = g_Pc[e * NLAB + l] - g_Pc[s * NLAB + l];
    out[tid] = g_Ps[s * NLAB + l] + g_Pe[e * NLAB + l]
             + __fdividef(diff, (float)w) + g_Pwb[w * NLAB + l];
}

// ---------------------------------------------------------------------------
extern "C" void kernel_launch(void* const* d_in, const int* in_sizes, int n_in,
                              void* d_out, int out_size) {
    const float* seq = (const float*)d_in[0];   // [1,512,768]
    const int*   st  = (const int*)  d_in[1];   // [32768]
    const int*   en  = (const int*)  d_in[2];   // [32768]
    const int*   wd  = (const int*)  d_in[3];   // [32768]
    const float* wt  = (const float*)d_in[4];   // [17,50]
    const float* W   = (const float*)d_in[5];   // [9,2354]
    const float* b   = (const float*)d_in[6];   // [9]
    float* out = (float*)d_out;                 // [32768,9]

    dim3 g1(SEQ_LEN / 8, NCHUNK);
    token_proj_kernel<<<g1, 256>>>(seq, W);
    reduce_kernel<<<(SEQ_LEN * 27 + 255) / 256, 256>>>();
    scan_width_kernel<<<1, 512>>>(wt, W, b);
    const int total = NSPANS * NLAB;
    assemble_kernel<<<(total + 255) / 256, 256>>>(st, en, wd, out);
}